// round 11
// baseline (speedup 1.0000x reference)
#include <cuda_runtime.h>

// YOLO v1 loss, S=7, B=2, C=20.
// Round 11: warp-private TMA pipelines. Each warp owns an NST=3 ring of
// 32-cell tiles (3840 B per array) with its own mbarriers; no __syncthreads
// in the main loop. 4 warps x 2 CTAs = 8 independent demand queues per SM
// (the queue count is the only lever that has moved DRAM% all session).

#define LAMBDA_COORD 5.0f
#define LAMBDA_NOOBJ 0.5f

#define WCPB     32                  // cells per warp-tile
#define THREADS  128
#define NWARP    (THREADS / 32)
#define NST      3                   // pipeline stages per warp
#define WT_FLOATS (WCPB * 30)        // 960 floats
#define WT_BYTES  (WT_FLOATS * 4)    // 3840 B

// ---- PTX helpers ----
static __device__ __forceinline__ unsigned smem_u32(const void* p) {
    return (unsigned)__cvta_generic_to_shared(p);
}
static __device__ __forceinline__ void mbar_init(unsigned mbar, unsigned count) {
    asm volatile("mbarrier.init.shared.b64 [%0], %1;" :: "r"(mbar), "r"(count) : "memory");
}
static __device__ __forceinline__ void mbar_expect_tx(unsigned mbar, unsigned bytes) {
    asm volatile("mbarrier.arrive.expect_tx.shared.b64 _, [%0], %1;"
                 :: "r"(mbar), "r"(bytes) : "memory");
}
static __device__ __forceinline__ void mbar_wait(unsigned mbar, unsigned parity) {
    unsigned done;
    asm volatile(
        "{\n\t.reg .pred p;\n\t"
        "mbarrier.try_wait.parity.acquire.cta.shared::cta.b64 p, [%1], %2;\n\t"
        "selp.b32 %0, 1, 0, p;\n\t}"
        : "=r"(done) : "r"(mbar), "r"(parity) : "memory");
    while (!done) {
        asm volatile(
            "{\n\t.reg .pred p;\n\t"
            "mbarrier.try_wait.parity.acquire.cta.shared::cta.b64 p, [%1], %2, 0x989680;\n\t"
            "selp.b32 %0, 1, 0, p;\n\t}"
            : "=r"(done) : "r"(mbar), "r"(parity) : "memory");
    }
}
static __device__ __forceinline__ void bulk_g2s(unsigned dst_smem, const void* src,
                                                unsigned bytes, unsigned mbar) {
    asm volatile(
        "cp.async.bulk.shared::cluster.global.mbarrier::complete_tx::bytes [%0], [%1], %2, [%3];"
        :: "r"(dst_smem), "l"(src), "r"(bytes), "r"(mbar) : "memory");
}
static __device__ __forceinline__ void fence_proxy_async_cta() {
    asm volatile("fence.proxy.async.shared::cta;" ::: "memory");
}

// ---- per-cell loss (smem pointers, 8B-aligned) ----
static __device__ __forceinline__ float cell_loss(const float* __restrict__ p,
                                                  const float* __restrict__ l,
                                                  int n)
{
    const float INV_S = 1.0f / 7.0f;

    float2 l45 = *(const float2*)(l + 4);   // l[4]=obj (0/1)
    float obj = l45.x;

    if (obj == 0.0f) {
        float2 p45 = *(const float2*)(p + 4);
        float2 p89 = *(const float2*)(p + 8);
        float pc0 = p45.x, pc1 = p89.y;
        return LAMBDA_NOOBJ * (pc0 * pc0 + pc1 * pc1);
    }

    int within = n % 49;
    float gx = (float)(within % 7);
    float gy = (float)(within / 7);

    float2 p01 = *(const float2*)(p + 0);
    float2 p23 = *(const float2*)(p + 2);
    float2 p45 = *(const float2*)(p + 4);
    float2 p67 = *(const float2*)(p + 6);
    float2 p89 = *(const float2*)(p + 8);
    float px0 = p01.x, py0 = p01.y, pw0 = p23.x, ph0 = p23.y, pc0 = p45.x;
    float px1 = p45.y, py1 = p67.x, pw1 = p67.y, ph1 = p89.x, pc1 = p89.y;

    float2 l01 = *(const float2*)(l + 0);
    float2 l23 = *(const float2*)(l + 2);
    float lx = l01.x, ly = l01.y, lw = l23.x, lh = l23.y;

    float l_cx = (gx + lx) * INV_S, l_cy = (gy + ly) * INV_S;
    float lminx = l_cx - lw * 0.5f, lmaxx = l_cx + lw * 0.5f;
    float lminy = l_cy - lh * 0.5f, lmaxy = l_cy + lh * 0.5f;
    float area_l = lw * lh;

    float cx0 = (gx + px0) * INV_S, cy0 = (gy + py0) * INV_S;
    float iw0 = fminf(cx0 + pw0 * 0.5f, lmaxx) - fmaxf(cx0 - pw0 * 0.5f, lminx);
    float ih0 = fminf(cy0 + ph0 * 0.5f, lmaxy) - fmaxf(cy0 - ph0 * 0.5f, lminy);
    float inter0 = fmaxf(iw0, 0.0f) * fmaxf(ih0, 0.0f);
    float den0 = pw0 * ph0 + area_l - inter0 + 1e-10f;

    float cx1 = (gx + px1) * INV_S, cy1 = (gy + py1) * INV_S;
    float iw1 = fminf(cx1 + pw1 * 0.5f, lmaxx) - fmaxf(cx1 - pw1 * 0.5f, lminx);
    float ih1 = fminf(cy1 + ph1 * 0.5f, lmaxy) - fmaxf(cy1 - ph1 * 0.5f, lminy);
    float inter1 = fmaxf(iw1, 0.0f) * fmaxf(ih1, 0.0f);
    float den1 = pw1 * ph1 + area_l - inter1 + 1e-10f;

    // argmax(iou), first-wins tie-break, denominators strictly positive
    bool sel1 = (inter1 * den0) > (inter0 * den1);

    float interR = sel1 ? inter1 : inter0;
    float denR   = sel1 ? den1   : den0;
    float iouR   = __fdividef(interR, denR);

    float pxr = sel1 ? px1 : px0;
    float pyr = sel1 ? py1 : py0;
    float pwr = sel1 ? pw1 : pw0;
    float phr = sel1 ? ph1 : ph0;
    float pcr = sel1 ? pc1 : pc0;
    float pco = sel1 ? pc0 : pc1;

    float dx = pxr - lx, dy = pyr - ly;
    float wh_err = (pwr + lw - 2.0f * sqrtf(pwr * lw))
                 + (phr + lh - 2.0f * sqrtf(phr * lh));
    float dconf = pcr - iouR;

    float acc = LAMBDA_COORD * (dx * dx + dy * dy + wh_err)
              + dconf * dconf
              + LAMBDA_NOOBJ * (pco * pco);

    #pragma unroll
    for (int k = 0; k < 10; k++) {
        float2 pp = *(const float2*)(p + 10 + 2 * k);
        float2 ll = *(const float2*)(l + 10 + 2 * k);
        float d0 = pp.x - ll.x;
        float d1 = pp.y - ll.y;
        acc += d0 * d0 + d1 * d1;
    }
    return acc;
}

__global__ __launch_bounds__(THREADS, 2)
void yolo_loss_kernel(const float* __restrict__ preds,
                      const float* __restrict__ labels,
                      float* __restrict__ out,
                      int nwtiles, int ncells, float inv_bs)
{
    extern __shared__ float dyn[];
    // layout: [NWARP][NST] preds warp-tiles, then [NWARP][NST] labels tiles
    __shared__ __align__(8) unsigned long long mbar_store[NWARP * NST];

    const int tid  = threadIdx.x;
    const int w    = tid >> 5;
    const int lane = tid & 31;

    // this warp's stage buffers and barriers
    float* wp = dyn + (w * NST) * WT_FLOATS;                      // preds ring
    float* wl = dyn + (NWARP * NST + w * NST) * WT_FLOATS;        // labels ring
    unsigned mb[NST];
    #pragma unroll
    for (int s = 0; s < NST; s++) mb[s] = smem_u32(&mbar_store[w * NST + s]);

    if (tid == 0) {
        for (int i = 0; i < NWARP * NST; i++)
            mbar_init(smem_u32(&mbar_store[i]), 1);
        fence_proxy_async_cta();
    }
    __syncthreads();

    // queue id for this warp; warp-tile t handled by queue t % NQ
    const int qid = blockIdx.x * NWARP + w;
    const int NQ  = gridDim.x * NWARP;

    // prefetch first NST warp-tiles
    if (lane == 0) {
        #pragma unroll
        for (int s = 0; s < NST; s++) {
            int t = qid + s * NQ;
            if (t < nwtiles) {
                mbar_expect_tx(mb[s], 2 * WT_BYTES);
                bulk_g2s(smem_u32(wp + s * WT_FLOATS),
                         preds + (size_t)t * WT_FLOATS, WT_BYTES, mb[s]);
                bulk_g2s(smem_u32(wl + s * WT_FLOATS),
                         labels + (size_t)t * WT_FLOATS, WT_BYTES, mb[s]);
            }
        }
    }

    float acc = 0.0f;
    unsigned ph = 0;          // per-stage phase bits (per-thread, consistent in warp)
    int s = 0;

    for (int t = qid; t < nwtiles; t += NQ) {
        mbar_wait(mb[s], (ph >> s) & 1u);
        ph ^= (1u << s);

        const float* sp = wp + s * WT_FLOATS + lane * 30;
        const float* sl = wl + s * WT_FLOATS + lane * 30;
        acc += cell_loss(sp, sl, t * WCPB + lane);

        __syncwarp();         // whole warp done reading stage s

        int tn = t + NST * NQ;
        if (lane == 0 && tn < nwtiles) {
            mbar_expect_tx(mb[s], 2 * WT_BYTES);
            bulk_g2s(smem_u32(wp + s * WT_FLOATS),
                     preds + (size_t)tn * WT_FLOATS, WT_BYTES, mb[s]);
            bulk_g2s(smem_u32(wl + s * WT_FLOATS),
                     labels + (size_t)tn * WT_FLOATS, WT_BYTES, mb[s]);
        }
        s = (s + 1 == NST) ? 0 : s + 1;
    }

    // tail cells (none for this shape: 802816 % 32 == 0, but be safe)
    if (blockIdx.x == 0 && w == 0) {
        int c = nwtiles * WCPB + lane;
        if (c < ncells)
            acc += cell_loss(preds + (size_t)c * 30, labels + (size_t)c * 30, c);
    }

    // warp reduce, then block combine
    #pragma unroll
    for (int o = 16; o > 0; o >>= 1)
        acc += __shfl_down_sync(0xffffffffu, acc, o);

    __shared__ float wsum[NWARP];
    if (lane == 0) wsum[w] = acc;
    __syncthreads();

    if (tid == 0) {
        float v = wsum[0] + wsum[1] + wsum[2] + wsum[3];
        atomicAdd(out, v * inv_bs);
    }
}

extern "C" void kernel_launch(void* const* d_in, const int* in_sizes, int n_in,
                              void* d_out, int out_size)
{
    const float* preds  = (const float*)d_in[0];
    const float* labels = (const float*)d_in[1];
    float* out = (float*)d_out;

    int ncells = in_sizes[0] / 30;          // bs * 7 * 7
    int bs     = ncells / 49;
    float inv_bs = 1.0f / (float)bs;
    int nwtiles = ncells / WCPB;            // 25088 warp-tiles for this shape

    int nsm = 148;
    cudaDeviceGetAttribute(&nsm, cudaDevAttrMultiProcessorCount, 0);

    const int smem_bytes = 2 * NWARP * NST * WT_BYTES;   // 92160 per CTA
    cudaFuncSetAttribute(yolo_loss_kernel,
                         cudaFuncAttributeMaxDynamicSharedMemorySize, smem_bytes);

    cudaMemsetAsync(out, 0, (size_t)out_size * sizeof(float));

    int grid = 2 * nsm;                      // 2 CTAs per SM
    if (grid < 1) grid = 1;
    yolo_loss_kernel<<<grid, THREADS, smem_bytes>>>(preds, labels, out,
                                                    nwtiles, ncells, inv_bs);
}

// round 12
// speedup vs baseline: 1.0684x; 1.0684x over previous
#include <cuda_runtime.h>

// YOLO v1 loss, S=7, B=2, C=20.
// Round 12: controlled recombination. R6 structure (CPB=128, NST=2, 128 thr,
// 61440B smem, proven memset + per-CTA atomicAdd epilogue) with R7's grid:
// the largest divisor of ntiles <= 3*nsm (448 for this shape -> exactly 14
// tiles per CTA, no straggler round). R7/R8 isolated the even-split as worth
// ~1.2us and the fused-reduction tail as the regression; this takes only the
// good half.

#define LAMBDA_COORD 5.0f
#define LAMBDA_NOOBJ 0.5f

#define CPB      128                 // cells per tile
#define THREADS  128
#define NST      2                   // pipeline stages
#define TILE_FLOATS (CPB * 30)       // 3840 floats
#define TILE_BYTES  (TILE_FLOATS * 4)  // 15360 B

// ---- PTX helpers ----
static __device__ __forceinline__ unsigned smem_u32(const void* p) {
    return (unsigned)__cvta_generic_to_shared(p);
}
static __device__ __forceinline__ void mbar_init(unsigned mbar, unsigned count) {
    asm volatile("mbarrier.init.shared.b64 [%0], %1;" :: "r"(mbar), "r"(count) : "memory");
}
static __device__ __forceinline__ void mbar_expect_tx(unsigned mbar, unsigned bytes) {
    asm volatile("mbarrier.arrive.expect_tx.shared.b64 _, [%0], %1;"
                 :: "r"(mbar), "r"(bytes) : "memory");
}
static __device__ __forceinline__ void mbar_wait(unsigned mbar, unsigned parity) {
    unsigned done;
    asm volatile(
        "{\n\t.reg .pred p;\n\t"
        "mbarrier.try_wait.parity.acquire.cta.shared::cta.b64 p, [%1], %2;\n\t"
        "selp.b32 %0, 1, 0, p;\n\t}"
        : "=r"(done) : "r"(mbar), "r"(parity) : "memory");
    while (!done) {
        asm volatile(
            "{\n\t.reg .pred p;\n\t"
            "mbarrier.try_wait.parity.acquire.cta.shared::cta.b64 p, [%1], %2, 0x989680;\n\t"
            "selp.b32 %0, 1, 0, p;\n\t}"
            : "=r"(done) : "r"(mbar), "r"(parity) : "memory");
    }
}
static __device__ __forceinline__ void bulk_g2s(unsigned dst_smem, const void* src,
                                                unsigned bytes, unsigned mbar) {
    asm volatile(
        "cp.async.bulk.shared::cluster.global.mbarrier::complete_tx::bytes [%0], [%1], %2, [%3];"
        :: "r"(dst_smem), "l"(src), "r"(bytes), "r"(mbar) : "memory");
}
static __device__ __forceinline__ void fence_proxy_async_cta() {
    asm volatile("fence.proxy.async.shared::cta;" ::: "memory");
}

// ---- per-cell loss (smem pointers, 8B-aligned) ----
static __device__ __forceinline__ float cell_loss(const float* __restrict__ p,
                                                  const float* __restrict__ l,
                                                  int n)
{
    const float INV_S = 1.0f / 7.0f;

    float2 l45 = *(const float2*)(l + 4);   // l[4]=obj (0/1)
    float obj = l45.x;

    if (obj == 0.0f) {
        float2 p45 = *(const float2*)(p + 4);
        float2 p89 = *(const float2*)(p + 8);
        float pc0 = p45.x, pc1 = p89.y;
        return LAMBDA_NOOBJ * (pc0 * pc0 + pc1 * pc1);
    }

    int within = n % 49;
    float gx = (float)(within % 7);
    float gy = (float)(within / 7);

    float2 p01 = *(const float2*)(p + 0);
    float2 p23 = *(const float2*)(p + 2);
    float2 p45 = *(const float2*)(p + 4);
    float2 p67 = *(const float2*)(p + 6);
    float2 p89 = *(const float2*)(p + 8);
    float px0 = p01.x, py0 = p01.y, pw0 = p23.x, ph0 = p23.y, pc0 = p45.x;
    float px1 = p45.y, py1 = p67.x, pw1 = p67.y, ph1 = p89.x, pc1 = p89.y;

    float2 l01 = *(const float2*)(l + 0);
    float2 l23 = *(const float2*)(l + 2);
    float lx = l01.x, ly = l01.y, lw = l23.x, lh = l23.y;

    float l_cx = (gx + lx) * INV_S, l_cy = (gy + ly) * INV_S;
    float lminx = l_cx - lw * 0.5f, lmaxx = l_cx + lw * 0.5f;
    float lminy = l_cy - lh * 0.5f, lmaxy = l_cy + lh * 0.5f;
    float area_l = lw * lh;

    float cx0 = (gx + px0) * INV_S, cy0 = (gy + py0) * INV_S;
    float iw0 = fminf(cx0 + pw0 * 0.5f, lmaxx) - fmaxf(cx0 - pw0 * 0.5f, lminx);
    float ih0 = fminf(cy0 + ph0 * 0.5f, lmaxy) - fmaxf(cy0 - ph0 * 0.5f, lminy);
    float inter0 = fmaxf(iw0, 0.0f) * fmaxf(ih0, 0.0f);
    float den0 = pw0 * ph0 + area_l - inter0 + 1e-10f;

    float cx1 = (gx + px1) * INV_S, cy1 = (gy + py1) * INV_S;
    float iw1 = fminf(cx1 + pw1 * 0.5f, lmaxx) - fmaxf(cx1 - pw1 * 0.5f, lminx);
    float ih1 = fminf(cy1 + ph1 * 0.5f, lmaxy) - fmaxf(cy1 - ph1 * 0.5f, lminy);
    float inter1 = fmaxf(iw1, 0.0f) * fmaxf(ih1, 0.0f);
    float den1 = pw1 * ph1 + area_l - inter1 + 1e-10f;

    // argmax(iou), first-wins tie-break, denominators strictly positive
    bool sel1 = (inter1 * den0) > (inter0 * den1);

    float interR = sel1 ? inter1 : inter0;
    float denR   = sel1 ? den1   : den0;
    float iouR   = __fdividef(interR, denR);

    float pxr = sel1 ? px1 : px0;
    float pyr = sel1 ? py1 : py0;
    float pwr = sel1 ? pw1 : pw0;
    float phr = sel1 ? ph1 : ph0;
    float pcr = sel1 ? pc1 : pc0;
    float pco = sel1 ? pc0 : pc1;

    float dx = pxr - lx, dy = pyr - ly;
    float wh_err = (pwr + lw - 2.0f * sqrtf(pwr * lw))
                 + (phr + lh - 2.0f * sqrtf(phr * lh));
    float dconf = pcr - iouR;

    float acc = LAMBDA_COORD * (dx * dx + dy * dy + wh_err)
              + dconf * dconf
              + LAMBDA_NOOBJ * (pco * pco);

    #pragma unroll
    for (int k = 0; k < 10; k++) {
        float2 pp = *(const float2*)(p + 10 + 2 * k);
        float2 ll = *(const float2*)(l + 10 + 2 * k);
        float d0 = pp.x - ll.x;
        float d1 = pp.y - ll.y;
        acc += d0 * d0 + d1 * d1;
    }
    return acc;
}

__global__ __launch_bounds__(THREADS, 3)
void yolo_loss_kernel(const float* __restrict__ preds,
                      const float* __restrict__ labels,
                      float* __restrict__ out,
                      int ntiles, int ncells, float inv_bs)
{
    extern __shared__ float dyn[];
    // layout: NST preds tiles, then NST labels tiles
    __shared__ __align__(8) unsigned long long mbar_store[NST];

    const int tid = threadIdx.x;

    unsigned mb[NST];
    #pragma unroll
    for (int s = 0; s < NST; s++) mb[s] = smem_u32(&mbar_store[s]);

    if (tid == 0) {
        #pragma unroll
        for (int s = 0; s < NST; s++) mbar_init(mb[s], 1);
        fence_proxy_async_cta();
    }
    __syncthreads();

    // prefetch first NST tiles (tile g handled by CTA g % gridDim)
    if (tid == 0) {
        #pragma unroll
        for (int s = 0; s < NST; s++) {
            int g = blockIdx.x + s * gridDim.x;
            if (g < ntiles) {
                mbar_expect_tx(mb[s], 2 * TILE_BYTES);
                bulk_g2s(smem_u32(dyn + s * TILE_FLOATS),
                         preds + (size_t)g * TILE_FLOATS, TILE_BYTES, mb[s]);
                bulk_g2s(smem_u32(dyn + (NST + s) * TILE_FLOATS),
                         labels + (size_t)g * TILE_FLOATS, TILE_BYTES, mb[s]);
            }
        }
    }

    float acc = 0.0f;
    unsigned ph = 0;          // per-stage phase bits
    int s = 0;

    for (int g = blockIdx.x; g < ntiles; g += gridDim.x) {
        mbar_wait(mb[s], (ph >> s) & 1u);
        ph ^= (1u << s);

        const float* sp = dyn + s * TILE_FLOATS + tid * 30;
        const float* sl = dyn + (NST + s) * TILE_FLOATS + tid * 30;
        acc += cell_loss(sp, sl, g * CPB + tid);

        __syncthreads();      // everyone done reading stage s

        int gn = g + NST * gridDim.x;
        if (tid == 0 && gn < ntiles) {
            mbar_expect_tx(mb[s], 2 * TILE_BYTES);
            bulk_g2s(smem_u32(dyn + s * TILE_FLOATS),
                     preds + (size_t)gn * TILE_FLOATS, TILE_BYTES, mb[s]);
            bulk_g2s(smem_u32(dyn + (NST + s) * TILE_FLOATS),
                     labels + (size_t)gn * TILE_FLOATS, TILE_BYTES, mb[s]);
        }
        s ^= 1;
    }

    // tail cells (none for this shape, but be safe)
    if (blockIdx.x == 0) {
        int c = ntiles * CPB + tid;
        if (c < ncells)
            acc += cell_loss(preds + (size_t)c * 30, labels + (size_t)c * 30, c);
    }

    // block reduction (128 threads = 4 warps)
    #pragma unroll
    for (int o = 16; o > 0; o >>= 1)
        acc += __shfl_down_sync(0xffffffffu, acc, o);

    __shared__ float wsum[THREADS / 32];
    int lane = tid & 31;
    int wid  = tid >> 5;
    if (lane == 0) wsum[wid] = acc;
    __syncthreads();

    if (tid == 0) {
        float v = wsum[0] + wsum[1] + wsum[2] + wsum[3];
        atomicAdd(out, v * inv_bs);
    }
}

extern "C" void kernel_launch(void* const* d_in, const int* in_sizes, int n_in,
                              void* d_out, int out_size)
{
    const float* preds  = (const float*)d_in[0];
    const float* labels = (const float*)d_in[1];
    float* out = (float*)d_out;

    int ncells = in_sizes[0] / 30;          // bs * 7 * 7
    int bs     = ncells / 49;
    float inv_bs = 1.0f / (float)bs;
    int ntiles = ncells / CPB;              // 6272 full tiles for this shape

    int nsm = 148;
    cudaDeviceGetAttribute(&nsm, cudaDevAttrMultiProcessorCount, 0);

    const int smem_bytes = 2 * NST * TILE_BYTES;   // 61440 per CTA
    cudaFuncSetAttribute(yolo_loss_kernel,
                         cudaFuncAttributeMaxDynamicSharedMemorySize, smem_bytes);

    cudaMemsetAsync(out, 0, (size_t)out_size * sizeof(float));

    // grid: largest divisor of ntiles that fits <= 3 CTAs/SM (448 for 6272
    // -> exactly 14 tiles/CTA, zero straggler round). Fall back to 3*nsm if
    // no divisor is within 25%.
    int gmax = 3 * nsm;
    if (gmax > ntiles && ntiles > 0) gmax = ntiles;
    if (gmax < 1) gmax = 1;
    int grid = 0;
    for (int g = gmax; g >= (3 * gmax) / 4 && g > 0; g--) {
        if (ntiles % g == 0) { grid = g; break; }
    }
    if (grid == 0) grid = gmax;

    yolo_loss_kernel<<<grid, THREADS, smem_bytes>>>(preds, labels, out,
                                                    ntiles, ncells, inv_bs);
}